// round 12
// baseline (speedup 1.0000x reference)
#include <cuda_runtime.h>
#include <cstdint>

#define NPIL   96000
#define MPTS   32
#define BATCH  8
#define NXc    432
#define NYc    496
#define NYNX   (NYc*NXc)          /* 214272 */
#define NCH    64
#define WCHUNK 256
#define NWCHUNK (NYNX / WCHUNK)   /* 837 exactly */
#define WMAX   64
#define WPITCH 65

// ---------------- device scratch (static, no allocation) ----------------
__device__ double d_stats[65];
__device__ float4 d_wbuf4[NPIL * 2];          // per pillar: (mx,my,mz,0),(cx,cy,cz,0)
__device__ int    d_winner[BATCH * NYNX];     // 6.9 MB
__device__ unsigned long long d_UPK[32 * 4];  // channel-pair packed UNSCALED u (A,B,C,D)
__device__ unsigned long long d_GPK[32 * 7];  // channel-pair packed s*g0..g5, t
__device__ unsigned long long d_SPK[32];      // channel-pair packed s

// ---------------- f32x2 helpers ----------------
__device__ __forceinline__ unsigned long long splat2(float v) {
    unsigned long long r;
    asm("mov.b64 %0, {%1,%1};" : "=l"(r) : "f"(v));
    return r;
}
__device__ __forceinline__ unsigned long long pack2(float lo, float hi) {
    unsigned long long r;
    asm("mov.b64 %0, {%1,%2};" : "=l"(r) : "f"(lo), "f"(hi));
    return r;
}
#define FMA2(d, a, b)  asm("fma.rn.f32x2 %0, %1, %2, %0;" : "+l"(d) : "l"(a), "l"(b))
#define MUL2(d, a, b)  asm("mul.rn.f32x2 %0, %1, %2;"     : "=l"(d) : "l"(a), "l"(b))
#define UNPK2(lo, hi, d) asm("mov.b64 {%0,%1}, %2;" : "=f"(lo), "=f"(hi) : "l"(d))

// ---------------- pre-init: winner=-1, stats=0, pack unscaled U ----------------
__global__ void pre_init_kernel(const float* __restrict__ W) {
    int i = blockIdx.x * blockDim.x + threadIdx.x;
    int stride = gridDim.x * blockDim.x;
    const int nw = BATCH * NYNX;
    int4* w4 = (int4*)d_winner;
    int4 m1 = make_int4(-1, -1, -1, -1);
    for (int j = i; j < nw / 4; j += stride) w4[j] = m1;
    if (blockIdx.x == 0) {
        if (threadIdx.x < 65) d_stats[threadIdx.x] = 0.0;
        if (threadIdx.x >= 128 && threadIdx.x < 160) {
            int t = threadIdx.x - 128;
            int c0 = 2 * t, c1 = 2 * t + 1;
            float u0[4], u1[4];
            u0[0] = W[0*NCH+c0] + W[4*NCH+c0] + W[7*NCH+c0];
            u0[1] = W[1*NCH+c0] + W[5*NCH+c0] + W[8*NCH+c0];
            u0[2] = W[2*NCH+c0] + W[6*NCH+c0] + W[9*NCH+c0];
            u0[3] = W[3*NCH+c0];
            u1[0] = W[0*NCH+c1] + W[4*NCH+c1] + W[7*NCH+c1];
            u1[1] = W[1*NCH+c1] + W[5*NCH+c1] + W[8*NCH+c1];
            u1[2] = W[2*NCH+c1] + W[6*NCH+c1] + W[9*NCH+c1];
            u1[3] = W[3*NCH+c1];
#pragma unroll
            for (int k = 0; k < 4; k++) d_UPK[t*4 + k] = pack2(u0[k], u1[k]);
        }
    }
}

// ---------------- stats + winner + wbuf: one pass over pillar data ----------------
__global__ void __launch_bounds__(256) stats_kernel(const float4* __restrict__ pil4,
                             const int4*  __restrict__ coords4,
                             const int*   __restrict__ nump) {
    __shared__ float sred[8][65];
    int p = blockIdx.x * blockDim.x + threadIdx.x;
    int lane = threadIdx.x & 31;
    int warp = threadIdx.x >> 5;

    float acc[65];
#pragma unroll
    for (int i = 0; i < 65; i++) acc[i] = 0.f;

    if (p < NPIL) {
        float sx=0.f, sy=0.f, sz=0.f, sw=0.f;
        float xx=0.f,xy=0.f,xz=0.f,xw=0.f,yy=0.f,yz=0.f,yw=0.f,zz=0.f,zw=0.f,ww=0.f;
        const float4* vp = pil4 + (size_t)p * MPTS;
#pragma unroll 16
        for (int m = 0; m < MPTS; m++) {
            float4 v = vp[m];
            sx += v.x; sy += v.y; sz += v.z; sw += v.w;
            xx = fmaf(v.x, v.x, xx); xy = fmaf(v.x, v.y, xy);
            xz = fmaf(v.x, v.z, xz); xw = fmaf(v.x, v.w, xw);
            yy = fmaf(v.y, v.y, yy); yz = fmaf(v.y, v.z, yz);
            yw = fmaf(v.y, v.w, yw);
            zz = fmaf(v.z, v.z, zz); zw = fmaf(v.z, v.w, zw);
            ww = fmaf(v.w, v.w, ww);
        }
        int4 cd = coords4[p];                // (b, z, y, x)

        // winner scatter-order emulation (last index wins)
        int cell = cd.y + cd.z * NXc + cd.w;
        atomicMax(&d_winner[cd.x * NYNX + cell], p);

        float n = (float)nump[p];
        float mx = sx / n, my = sy / n, mz = sz / n;
        float ctrx = (float)cd.w * 0.16f + 0.08f;
        float ctry = (float)cd.z * 0.16f + (-39.6f);
        float ctrz = (float)cd.y * 4.0f  + (-1.0f);

        float sv[4] = {sx, sy, sz, sw};
        float w6[6] = {mx, my, mz, ctrx, ctry, ctrz};

        acc[0]=sx; acc[1]=sy; acc[2]=sz; acc[3]=sw;
        acc[4]=xx; acc[5]=xy; acc[6]=xz; acc[7]=xw; acc[8]=yy;
        acc[9]=yz; acc[10]=yw; acc[11]=zz; acc[12]=zw; acc[13]=ww;
#pragma unroll
        for (int j = 0; j < 6; j++) acc[14 + j] = w6[j];
#pragma unroll
        for (int i = 0; i < 4; i++)
#pragma unroll
            for (int j = 0; j < 6; j++) acc[20 + i*6 + j] = sv[i] * w6[j];
        {
            int k = 0;
#pragma unroll
            for (int i = 0; i < 6; i++)
#pragma unroll
                for (int j = i; j < 6; j++) { acc[44 + k] = w6[i] * w6[j]; k++; }
        }
        d_wbuf4[p*2 + 0] = make_float4(mx, my, mz, 0.f);
        d_wbuf4[p*2 + 1] = make_float4(ctrx, ctry, ctrz, 0.f);
    }

    // warp tree-reduce all 65 partials
#pragma unroll
    for (int i = 0; i < 65; i++) {
        float v = acc[i];
        v += __shfl_xor_sync(0xffffffffu, v, 16);
        v += __shfl_xor_sync(0xffffffffu, v, 8);
        v += __shfl_xor_sync(0xffffffffu, v, 4);
        v += __shfl_xor_sync(0xffffffffu, v, 2);
        v += __shfl_xor_sync(0xffffffffu, v, 1);
        acc[i] = v;
    }
    if (lane == 0) {
#pragma unroll
        for (int i = 0; i < 65; i++) sred[warp][i] = acc[i];
    }
    __syncthreads();

    if (threadIdx.x < 65) {
        float s = 0.f;
#pragma unroll
        for (int w = 0; w < 8; w++) s += sred[w][threadIdx.x];
        atomicAdd(&d_stats[threadIdx.x], (double)s);
    }
}

// ---------------- finalize: closed-form BN params, channel-pair packed ----------------
__global__ void finalize_kernel(const float* __restrict__ W,
                                const float* __restrict__ gamma,
                                const float* __restrict__ beta) {
    __shared__ float s_g[NCH][6];
    __shared__ float s_t[NCH];
    __shared__ float s_s[NCH];

    int c = threadIdx.x;
    if (c < NCH) {
        double A = (double)W[0*NCH+c] + (double)W[4*NCH+c] + (double)W[7*NCH+c];
        double Bv= (double)W[1*NCH+c] + (double)W[5*NCH+c] + (double)W[8*NCH+c];
        double Cv= (double)W[2*NCH+c] + (double)W[6*NCH+c] + (double)W[9*NCH+c];
        double Dv= (double)W[3*NCH+c];
        double u[4] = {A, Bv, Cv, Dv};
        double g[6];
#pragma unroll
        for (int j = 0; j < 6; j++) g[j] = (double)W[(4 + j)*NCH + c];

        double st[65];
#pragma unroll
        for (int i = 0; i < 65; i++) st[i] = d_stats[i];

        double S1 = u[0]*st[0] + u[1]*st[1] + u[2]*st[2] + u[3]*st[3];
        double sg = 0.0;
#pragma unroll
        for (int j = 0; j < 6; j++) sg += g[j] * st[14 + j];
        S1 -= (double)MPTS * sg;

        double Q1 = st[4]*A*A + st[8]*Bv*Bv + st[11]*Cv*Cv + st[13]*Dv*Dv
                  + 2.0*(st[5]*A*Bv + st[6]*A*Cv + st[7]*A*Dv
                       + st[9]*Bv*Cv + st[10]*Bv*Dv + st[12]*Cv*Dv);
        double Q2 = 0.0;
#pragma unroll
        for (int i = 0; i < 4; i++)
#pragma unroll
            for (int j = 0; j < 6; j++) Q2 += u[i] * st[20 + i*6 + j] * g[j];
        double Q3 = 0.0;
        {
            int k = 0;
#pragma unroll
            for (int i = 0; i < 6; i++)
#pragma unroll
                for (int j = i; j < 6; j++) {
                    Q3 += (i == j ? 1.0 : 2.0) * g[i] * g[j] * st[44 + k];
                    k++;
                }
        }
        double S2 = Q1 - 2.0*Q2 + (double)MPTS * Q3;

        double N   = (double)NPIL * (double)MPTS;
        double mu  = S1 / N;
        double var = S2 / N - mu * mu;
        double s   = (double)gamma[c] / sqrt(var + 1e-3);
        double t   = (double)beta[c] - s * mu;

#pragma unroll
        for (int j = 0; j < 6; j++) s_g[c][j] = (float)(s * g[j]);
        s_t[c] = (float)t;
        s_s[c] = (float)s;
    }
    __syncthreads();

    if (c < 32) {
        int c0 = 2 * c, c1 = 2 * c + 1;
#pragma unroll
        for (int j = 0; j < 6; j++) d_GPK[c*7 + j] = pack2(s_g[c0][j], s_g[c1][j]);
        d_GPK[c*7 + 6] = pack2(s_t[c0], s_t[c1]);
        d_SPK[c] = pack2(s_s[c0], s_s[c1]);
    }
}

// ---------------- writer: fused GEMM+max+BN+relu per winner, coalesced stream ----------------
// phase 2: 16 threads per winner; thread g handles pairs {g, 16+g}
//          = channels {2g, 2g+1} and {32+2g, 32+2g+1}.
__global__ void __launch_bounds__(256) writer_kernel(const float4* __restrict__ pil4,
                                                     float* __restrict__ out) {
    __shared__ int   s_slot[WCHUNK];    // -1 zero, 0..WMAX-1 slot, -2 direct-stored
    __shared__ int2  s_list[WCHUNK];    // (cell_local, pillar)
    __shared__ float s_vals[NCH * WPITCH];
    __shared__ int   s_n;

    int t    = threadIdx.x;
    int lane = t & 31;
    int warp = t >> 5;
    int b    = blockIdx.y;
    int c0   = blockIdx.x * WCHUNK;
    size_t rowbase = (size_t)b * NCH * NYNX + c0;

    if (t == 0) s_n = 0;
    __syncthreads();

    // --- phase 1: winners (coalesced) ---
    {
        int w = d_winner[b * NYNX + c0 + t];
        int slot = -1;
        if (w >= 0) {
            slot = atomicAdd(&s_n, 1);
            s_list[slot] = make_int2(t, w);
            if (slot >= WMAX) slot = -2;
        }
        s_slot[t] = slot;
    }
    __syncthreads();
    int n = s_n;

    // --- phase 2: compute winner values (GEMM+max+affine+relu) ---
    {
        int g  = t & 15;
        int r0 = g, r1 = 16 + g;     // channel-pair indices

        unsigned long long ux0 = d_UPK[r0*4+0], uy0 = d_UPK[r0*4+1],
                           uz0 = d_UPK[r0*4+2], uw0 = d_UPK[r0*4+3];
        unsigned long long ux1 = d_UPK[r1*4+0], uy1 = d_UPK[r1*4+1],
                           uz1 = d_UPK[r1*4+2], uw1 = d_UPK[r1*4+3];

        for (int s = t >> 4; s < n; s += 16) {
            int2 e = s_list[s];
            int p = e.y;
            const float4* vp = pil4 + (size_t)p * MPTS;

            float q0 = -3.4e38f, q1 = -3.4e38f, q2 = -3.4e38f, q3 = -3.4e38f;
#pragma unroll 8
            for (int m = 0; m < MPTS; m++) {
                float4 v = __ldg(&vp[m]);
                unsigned long long vx = splat2(v.x);
                unsigned long long vy = splat2(v.y);
                unsigned long long vz = splat2(v.z);
                unsigned long long vw = splat2(v.w);
                unsigned long long d0, d1;
                MUL2(d0, vw, uw0); FMA2(d0, vz, uz0); FMA2(d0, vy, uy0); FMA2(d0, vx, ux0);
                MUL2(d1, vw, uw1); FMA2(d1, vz, uz1); FMA2(d1, vy, uy1); FMA2(d1, vx, ux1);
                float lo, hi;
                UNPK2(lo, hi, d0); q0 = fmaxf(q0, lo); q1 = fmaxf(q1, hi);
                UNPK2(lo, hi, d1); q2 = fmaxf(q2, lo); q3 = fmaxf(q3, hi);
            }

            // BN affine + relu
            float4 w0 = d_wbuf4[p*2 + 0];
            float4 w1 = d_wbuf4[p*2 + 1];
            unsigned long long nm0 = splat2(-w0.x), nm1 = splat2(-w0.y), nm2 = splat2(-w0.z);
            unsigned long long nc0 = splat2(-w1.x), nc1 = splat2(-w1.y), nc2 = splat2(-w1.z);

            float v4[4];
#pragma unroll
            for (int k = 0; k < 2; k++) {
                int r = (k == 0) ? r0 : r1;
                unsigned long long a = d_GPK[r*7 + 6];
                FMA2(a, nm0, d_GPK[r*7 + 0]);
                FMA2(a, nm1, d_GPK[r*7 + 1]);
                FMA2(a, nm2, d_GPK[r*7 + 2]);
                FMA2(a, nc0, d_GPK[r*7 + 3]);
                FMA2(a, nc1, d_GPK[r*7 + 4]);
                FMA2(a, nc2, d_GPK[r*7 + 5]);
                unsigned long long m = (k == 0) ? pack2(q0, q1) : pack2(q2, q3);
                FMA2(a, m, d_SPK[r]);
                float lo, hi;
                UNPK2(lo, hi, a);
                v4[2*k]     = fmaxf(lo, 0.f);
                v4[2*k + 1] = fmaxf(hi, 0.f);
            }

            int ch0 = 2 * r0;   // channels 2g, 2g+1
            int ch1 = 2 * r1;   // channels 32+2g, 32+2g+1
            if (s < WMAX) {
                s_vals[(ch0 + 0) * WPITCH + s] = v4[0];
                s_vals[(ch0 + 1) * WPITCH + s] = v4[1];
                s_vals[(ch1 + 0) * WPITCH + s] = v4[2];
                s_vals[(ch1 + 1) * WPITCH + s] = v4[3];
            } else {
                // overflow (astronomically rare): direct scattered store (all channels)
                out[rowbase + (size_t)(ch0 + 0) * NYNX + e.x] = v4[0];
                out[rowbase + (size_t)(ch0 + 1) * NYNX + e.x] = v4[1];
                out[rowbase + (size_t)(ch1 + 0) * NYNX + e.x] = v4[2];
                out[rowbase + (size_t)(ch1 + 1) * NYNX + e.x] = v4[3];
            }
        }
    }
    __syncthreads();

    // --- phase 3: stream all 64 channel rows. warp w -> channels 8w..8w+7 ---
    int4 sl0 = ((const int4*)s_slot)[lane];        // cells 4*lane .. 4*lane+3
    int4 sl1 = ((const int4*)s_slot)[lane + 32];   // cells 128+4*lane ..
    int mn0 = min(min(sl0.x, sl0.y), min(sl0.z, sl0.w));
    int mn1 = min(min(sl1.x, sl1.y), min(sl1.z, sl1.w));
#pragma unroll
    for (int r = 0; r < 8; r++) {
        int ch = warp * 8 + r;
        const float* vrow = &s_vals[ch * WPITCH];
        float* dst = out + rowbase + (size_t)ch * NYNX;

        float4 v0;
        v0.x = (sl0.x >= 0) ? vrow[sl0.x] : 0.f;
        v0.y = (sl0.y >= 0) ? vrow[sl0.y] : 0.f;
        v0.z = (sl0.z >= 0) ? vrow[sl0.z] : 0.f;
        v0.w = (sl0.w >= 0) ? vrow[sl0.w] : 0.f;
        if (mn0 > -2) {
            __stcs((float4*)(dst + lane * 4), v0);
        } else {
            if (sl0.x != -2) dst[lane*4 + 0] = v0.x;
            if (sl0.y != -2) dst[lane*4 + 1] = v0.y;
            if (sl0.z != -2) dst[lane*4 + 2] = v0.z;
            if (sl0.w != -2) dst[lane*4 + 3] = v0.w;
        }

        float4 v1;
        v1.x = (sl1.x >= 0) ? vrow[sl1.x] : 0.f;
        v1.y = (sl1.y >= 0) ? vrow[sl1.y] : 0.f;
        v1.z = (sl1.z >= 0) ? vrow[sl1.z] : 0.f;
        v1.w = (sl1.w >= 0) ? vrow[sl1.w] : 0.f;
        if (mn1 > -2) {
            __stcs((float4*)(dst + 128 + lane * 4), v1);
        } else {
            if (sl1.x != -2) dst[128 + lane*4 + 0] = v1.x;
            if (sl1.y != -2) dst[128 + lane*4 + 1] = v1.y;
            if (sl1.z != -2) dst[128 + lane*4 + 2] = v1.z;
            if (sl1.w != -2) dst[128 + lane*4 + 3] = v1.w;
        }
    }
}

// ---------------- launch: single stream, vals stage eliminated ----------------
extern "C" void kernel_launch(void* const* d_in, const int* in_sizes, int n_in,
                              void* d_out, int out_size) {
    const float4* pil4    = (const float4*)d_in[0];
    const int4*   coords4 = (const int4*)d_in[1];
    const int*    nump    = (const int*)d_in[2];
    const float*  W       = (const float*)d_in[3];
    const float*  gamma   = (const float*)d_in[4];
    const float*  beta    = (const float*)d_in[5];
    float* out = (float*)d_out;

    pre_init_kernel<<<592, 256>>>(W);
    stats_kernel<<<(NPIL + 255) / 256, 256>>>(pil4, coords4, nump);
    finalize_kernel<<<1, 64>>>(W, gamma, beta);
    dim3 grid(NWCHUNK, BATCH);
    writer_kernel<<<grid, 256>>>(pil4, out);
}

// round 13
// speedup vs baseline: 1.1373x; 1.1373x over previous
#include <cuda_runtime.h>
#include <cstdint>

#define NPIL   96000
#define MPTS   32
#define BATCH  8
#define NXc    432
#define NYc    496
#define NYNX   (NYc*NXc)          /* 214272 */
#define NCH    64
#define WCHUNK 384
#define NWCHUNK (NYNX / WCHUNK)   /* 558 exactly */
#define WMAX   64
#define WPITCH 65

// ---------------- device scratch (static, no allocation) ----------------
__device__ double d_stats[65];
__device__ float4 d_wbuf4[NPIL * 2];          // per pillar: (mx,my,mz,0),(cx,cy,cz,0)
__device__ int    d_winner[BATCH * NYNX];     // 6.9 MB
__device__ float4 d_vals4[NPIL * 16];         // 24.6 MB: per pillar 64 UNSCALED channel maxes (pair-ordered)
__device__ unsigned long long d_UPK[32 * 4];  // channel-pair packed UNSCALED u (A,B,C,D)
__device__ unsigned long long d_GPK[32 * 7];  // channel-pair packed s*g0..g5, t
__device__ unsigned long long d_SPK[32];      // channel-pair packed s

// ---------------- f32x2 helpers ----------------
__device__ __forceinline__ unsigned long long splat2(float v) {
    unsigned long long r;
    asm("mov.b64 %0, {%1,%1};" : "=l"(r) : "f"(v));
    return r;
}
__device__ __forceinline__ unsigned long long pack2(float lo, float hi) {
    unsigned long long r;
    asm("mov.b64 %0, {%1,%2};" : "=l"(r) : "f"(lo), "f"(hi));
    return r;
}
#define FMA2(d, a, b)  asm("fma.rn.f32x2 %0, %1, %2, %0;" : "+l"(d) : "l"(a), "l"(b))
#define MUL2(d, a, b)  asm("mul.rn.f32x2 %0, %1, %2;"     : "=l"(d) : "l"(a), "l"(b))
#define UNPK2(lo, hi, d) asm("mov.b64 {%0,%1}, %2;" : "=f"(lo), "=f"(hi) : "l"(d))

// ---------------- pre-init: winner=-1, stats=0, pack unscaled U ----------------
__global__ void pre_init_kernel(const float* __restrict__ W) {
    int i = blockIdx.x * blockDim.x + threadIdx.x;
    int stride = gridDim.x * blockDim.x;
    const int nw = BATCH * NYNX;
    int4* w4 = (int4*)d_winner;
    int4 m1 = make_int4(-1, -1, -1, -1);
    for (int j = i; j < nw / 4; j += stride) w4[j] = m1;
    if (blockIdx.x == 0) {
        if (threadIdx.x < 65) d_stats[threadIdx.x] = 0.0;
        if (threadIdx.x >= 128 && threadIdx.x < 160) {
            int t = threadIdx.x - 128;
            int c0 = 2 * t, c1 = 2 * t + 1;
            float u0[4], u1[4];
            u0[0] = W[0*NCH+c0] + W[4*NCH+c0] + W[7*NCH+c0];
            u0[1] = W[1*NCH+c0] + W[5*NCH+c0] + W[8*NCH+c0];
            u0[2] = W[2*NCH+c0] + W[6*NCH+c0] + W[9*NCH+c0];
            u0[3] = W[3*NCH+c0];
            u1[0] = W[0*NCH+c1] + W[4*NCH+c1] + W[7*NCH+c1];
            u1[1] = W[1*NCH+c1] + W[5*NCH+c1] + W[8*NCH+c1];
            u1[2] = W[2*NCH+c1] + W[6*NCH+c1] + W[9*NCH+c1];
            u1[3] = W[3*NCH+c1];
#pragma unroll
            for (int k = 0; k < 4; k++) d_UPK[t*4 + k] = pack2(u0[k], u1[k]);
        }
    }
}

// ---------------- stats + winner + wbuf: one pass over pillar data ----------------
__global__ void __launch_bounds__(256) stats_kernel(const float4* __restrict__ pil4,
                             const int4*  __restrict__ coords4,
                             const int*   __restrict__ nump) {
    __shared__ float sred[8][65];
    int p = blockIdx.x * blockDim.x + threadIdx.x;
    int lane = threadIdx.x & 31;
    int warp = threadIdx.x >> 5;

    float acc[65];
#pragma unroll
    for (int i = 0; i < 65; i++) acc[i] = 0.f;

    if (p < NPIL) {
        float sx=0.f, sy=0.f, sz=0.f, sw=0.f;
        float xx=0.f,xy=0.f,xz=0.f,xw=0.f,yy=0.f,yz=0.f,yw=0.f,zz=0.f,zw=0.f,ww=0.f;
        const float4* vp = pil4 + (size_t)p * MPTS;
#pragma unroll 16
        for (int m = 0; m < MPTS; m++) {
            float4 v = vp[m];
            sx += v.x; sy += v.y; sz += v.z; sw += v.w;
            xx = fmaf(v.x, v.x, xx); xy = fmaf(v.x, v.y, xy);
            xz = fmaf(v.x, v.z, xz); xw = fmaf(v.x, v.w, xw);
            yy = fmaf(v.y, v.y, yy); yz = fmaf(v.y, v.z, yz);
            yw = fmaf(v.y, v.w, yw);
            zz = fmaf(v.z, v.z, zz); zw = fmaf(v.z, v.w, zw);
            ww = fmaf(v.w, v.w, ww);
        }
        int4 cd = coords4[p];                // (b, z, y, x)

        // winner scatter-order emulation (last index wins)
        int cell = cd.y + cd.z * NXc + cd.w;
        atomicMax(&d_winner[cd.x * NYNX + cell], p);

        float n = (float)nump[p];
        float mx = sx / n, my = sy / n, mz = sz / n;
        float ctrx = (float)cd.w * 0.16f + 0.08f;
        float ctry = (float)cd.z * 0.16f + (-39.6f);
        float ctrz = (float)cd.y * 4.0f  + (-1.0f);

        float sv[4] = {sx, sy, sz, sw};
        float w6[6] = {mx, my, mz, ctrx, ctry, ctrz};

        acc[0]=sx; acc[1]=sy; acc[2]=sz; acc[3]=sw;
        acc[4]=xx; acc[5]=xy; acc[6]=xz; acc[7]=xw; acc[8]=yy;
        acc[9]=yz; acc[10]=yw; acc[11]=zz; acc[12]=zw; acc[13]=ww;
#pragma unroll
        for (int j = 0; j < 6; j++) acc[14 + j] = w6[j];
#pragma unroll
        for (int i = 0; i < 4; i++)
#pragma unroll
            for (int j = 0; j < 6; j++) acc[20 + i*6 + j] = sv[i] * w6[j];
        {
            int k = 0;
#pragma unroll
            for (int i = 0; i < 6; i++)
#pragma unroll
                for (int j = i; j < 6; j++) { acc[44 + k] = w6[i] * w6[j]; k++; }
        }
        d_wbuf4[p*2 + 0] = make_float4(mx, my, mz, 0.f);
        d_wbuf4[p*2 + 1] = make_float4(ctrx, ctry, ctrz, 0.f);
    }

    // warp tree-reduce all 65 partials
#pragma unroll
    for (int i = 0; i < 65; i++) {
        float v = acc[i];
        v += __shfl_xor_sync(0xffffffffu, v, 16);
        v += __shfl_xor_sync(0xffffffffu, v, 8);
        v += __shfl_xor_sync(0xffffffffu, v, 4);
        v += __shfl_xor_sync(0xffffffffu, v, 2);
        v += __shfl_xor_sync(0xffffffffu, v, 1);
        acc[i] = v;
    }
    if (lane == 0) {
#pragma unroll
        for (int i = 0; i < 65; i++) sred[warp][i] = acc[i];
    }
    __syncthreads();

    if (threadIdx.x < 65) {
        float s = 0.f;
#pragma unroll
        for (int w = 0; w < 8; w++) s += sred[w][threadIdx.x];
        atomicAdd(&d_stats[threadIdx.x], (double)s);
    }
}

// ---------------- finalize: closed-form BN params, channel-pair packed ----------------
__global__ void finalize_kernel(const float* __restrict__ W,
                                const float* __restrict__ gamma,
                                const float* __restrict__ beta) {
    __shared__ float s_g[NCH][6];
    __shared__ float s_t[NCH];
    __shared__ float s_s[NCH];

    int c = threadIdx.x;
    if (c < NCH) {
        double A = (double)W[0*NCH+c] + (double)W[4*NCH+c] + (double)W[7*NCH+c];
        double Bv= (double)W[1*NCH+c] + (double)W[5*NCH+c] + (double)W[8*NCH+c];
        double Cv= (double)W[2*NCH+c] + (double)W[6*NCH+c] + (double)W[9*NCH+c];
        double Dv= (double)W[3*NCH+c];
        double u[4] = {A, Bv, Cv, Dv};
        double g[6];
#pragma unroll
        for (int j = 0; j < 6; j++) g[j] = (double)W[(4 + j)*NCH + c];

        double st[65];
#pragma unroll
        for (int i = 0; i < 65; i++) st[i] = d_stats[i];

        double S1 = u[0]*st[0] + u[1]*st[1] + u[2]*st[2] + u[3]*st[3];
        double sg = 0.0;
#pragma unroll
        for (int j = 0; j < 6; j++) sg += g[j] * st[14 + j];
        S1 -= (double)MPTS * sg;

        double Q1 = st[4]*A*A + st[8]*Bv*Bv + st[11]*Cv*Cv + st[13]*Dv*Dv
                  + 2.0*(st[5]*A*Bv + st[6]*A*Cv + st[7]*A*Dv
                       + st[9]*Bv*Cv + st[10]*Bv*Dv + st[12]*Cv*Dv);
        double Q2 = 0.0;
#pragma unroll
        for (int i = 0; i < 4; i++)
#pragma unroll
            for (int j = 0; j < 6; j++) Q2 += u[i] * st[20 + i*6 + j] * g[j];
        double Q3 = 0.0;
        {
            int k = 0;
#pragma unroll
            for (int i = 0; i < 6; i++)
#pragma unroll
                for (int j = i; j < 6; j++) {
                    Q3 += (i == j ? 1.0 : 2.0) * g[i] * g[j] * st[44 + k];
                    k++;
                }
        }
        double S2 = Q1 - 2.0*Q2 + (double)MPTS * Q3;

        double N   = (double)NPIL * (double)MPTS;
        double mu  = S1 / N;
        double var = S2 / N - mu * mu;
        double s   = (double)gamma[c] / sqrt(var + 1e-3);
        double t   = (double)beta[c] - s * mu;

#pragma unroll
        for (int j = 0; j < 6; j++) s_g[c][j] = (float)(s * g[j]);
        s_t[c] = (float)t;
        s_s[c] = (float)s;
    }
    __syncthreads();

    if (c < 32) {
        int c0 = 2 * c, c1 = 2 * c + 1;
#pragma unroll
        for (int j = 0; j < 6; j++) d_GPK[c*7 + j] = pack2(s_g[c0][j], s_g[c1][j]);
        d_GPK[c*7 + 6] = pack2(s_t[c0], s_t[c1]);
        d_SPK[c] = pack2(s_s[c0], s_s[c1]);
    }
}

// ---------------- vals: UNSCALED max_m(v.u) ; 8 threads/pillar x 8 channels ----------------
// u64 slot p*32+r holds channel pair r (channels 2r, 2r+1).
__global__ void __launch_bounds__(256) vals_kernel(const float4* __restrict__ pil4) {
    __shared__ float4 spts[32][33];   // 32 pillars/block, pitch 33 float4

    int tid = threadIdx.x;
    int pg  = tid >> 3;              // pillar slot 0..31
    int g   = tid & 7;               // channel group
    int pbase = blockIdx.x * 32;
    int p = pbase + pg;

    // load 32 pillars (1024 float4) with 256 threads, coalesced
#pragma unroll
    for (int k = 0; k < 4; k++) {
        int idx = tid + k * 256;
        spts[idx >> 5][idx & 31] = pil4[(size_t)(pbase + (idx >> 5)) * MPTS + (idx & 31)];
    }

    int pr[4] = {2*g, 2*g + 1, 16 + 2*g, 16 + 2*g + 1};

    unsigned long long ux[4], uy[4], uz[4], uw[4];
#pragma unroll
    for (int k = 0; k < 4; k++) {
        int r = pr[k];
        ux[k] = d_UPK[r*4 + 0];
        uy[k] = d_UPK[r*4 + 1];
        uz[k] = d_UPK[r*4 + 2];
        uw[k] = d_UPK[r*4 + 3];
    }

    __syncthreads();

    float q[8];
#pragma unroll
    for (int k = 0; k < 8; k++) q[k] = -3.4e38f;

#pragma unroll
    for (int m = 0; m < MPTS; m++) {
        float4 v = spts[pg][m];
        unsigned long long vx = splat2(v.x);
        unsigned long long vy = splat2(v.y);
        unsigned long long vz = splat2(v.z);
        unsigned long long vw = splat2(v.w);
#pragma unroll
        for (int k = 0; k < 4; k++) {
            unsigned long long d;
            MUL2(d, vw, uw[k]);
            FMA2(d, vz, uz[k]);
            FMA2(d, vy, uy[k]);
            FMA2(d, vx, ux[k]);
            float lo, hi;
            UNPK2(lo, hi, d);
            q[2*k]     = fmaxf(q[2*k],     lo);
            q[2*k + 1] = fmaxf(q[2*k + 1], hi);
        }
    }

    // pairs {2g,2g+1} at float4 idx g ; pairs {16+2g,16+2g+1} at idx 8+g
    d_vals4[(size_t)p * 16 + g]     = make_float4(q[0], q[1], q[2], q[3]);
    d_vals4[(size_t)p * 16 + 8 + g] = make_float4(q[4], q[5], q[6], q[7]);
}

// ---------------- writer: affine+relu per winner, then coalesced stream ----------------
// 256 threads, 384 cells per block (214272 = 384*558).
__global__ void __launch_bounds__(256) writer_kernel(float* __restrict__ out) {
    __shared__ int   s_slot[WCHUNK];    // -1 zero, 0..WMAX-1 slot, -2 direct-stored
    __shared__ int2  s_list[WCHUNK];    // (cell_local, pillar)
    __shared__ float s_vals[NCH * WPITCH];
    __shared__ int   s_n;

    int t    = threadIdx.x;
    int lane = t & 31;
    int warp = t >> 5;
    int b    = blockIdx.y;
    int c0   = blockIdx.x * WCHUNK;
    size_t rowbase = (size_t)b * NCH * NYNX + c0;

    if (t == 0) s_n = 0;
    __syncthreads();

    // --- phase 1: winners (coalesced) ---
    for (int i = t; i < WCHUNK; i += 256) {
        int w = d_winner[b * NYNX + c0 + i];
        int slot = -1;
        if (w >= 0) {
            slot = atomicAdd(&s_n, 1);
            s_list[slot] = make_int2(i, w);
            if (slot >= WMAX) slot = -2;
        }
        s_slot[i] = slot;
    }
    __syncthreads();
    int n = s_n;

    // --- phase 2: gather M rows, apply BN affine + relu ---
    for (int idx = t; idx < n * 16; idx += 256) {
        int s = idx >> 4;
        int j = idx & 15;
        int2 e = s_list[s];
        int p = e.y;

        // channels covered by this float4 (vals layout: idx j -> pairs)
        int cbase = (j < 8) ? (4*j) : (32 + 4*(j - 8));
        int r0 = cbase >> 1;          // pair indices r0, r0+1

        float4 w0 = d_wbuf4[p*2 + 0];
        float4 w1 = d_wbuf4[p*2 + 1];
        unsigned long long nm0 = splat2(-w0.x), nm1 = splat2(-w0.y), nm2 = splat2(-w0.z);
        unsigned long long nc0 = splat2(-w1.x), nc1 = splat2(-w1.y), nc2 = splat2(-w1.z);

        ulonglong2 M2 = ((const ulonglong2*)d_vals4)[(size_t)p * 16 + j];

        float v4[4];
#pragma unroll
        for (int k = 0; k < 2; k++) {
            int r = r0 + k;
            unsigned long long a = d_GPK[r*7 + 6];      // t2
            FMA2(a, nm0, d_GPK[r*7 + 0]);
            FMA2(a, nm1, d_GPK[r*7 + 1]);
            FMA2(a, nm2, d_GPK[r*7 + 2]);
            FMA2(a, nc0, d_GPK[r*7 + 3]);
            FMA2(a, nc1, d_GPK[r*7 + 4]);
            FMA2(a, nc2, d_GPK[r*7 + 5]);
            unsigned long long m = (k == 0) ? M2.x : M2.y;
            FMA2(a, m, d_SPK[r]);                       // s*M + cst
            float lo, hi;
            UNPK2(lo, hi, a);
            v4[2*k]     = fmaxf(lo, 0.f);
            v4[2*k + 1] = fmaxf(hi, 0.f);
        }

        if (s < WMAX) {
            s_vals[(cbase + 0) * WPITCH + s] = v4[0];
            s_vals[(cbase + 1) * WPITCH + s] = v4[1];
            s_vals[(cbase + 2) * WPITCH + s] = v4[2];
            s_vals[(cbase + 3) * WPITCH + s] = v4[3];
        } else {
            // overflow (astronomically rare): direct scattered store
            out[rowbase + (size_t)(cbase + 0) * NYNX + e.x] = v4[0];
            out[rowbase + (size_t)(cbase + 1) * NYNX + e.x] = v4[1];
            out[rowbase + (size_t)(cbase + 2) * NYNX + e.x] = v4[2];
            out[rowbase + (size_t)(cbase + 3) * NYNX + e.x] = v4[3];
        }
    }
    __syncthreads();

    // --- phase 3: stream all 64 channel rows. warp w -> channels 8w..8w+7 ---
    // 384 cells = 96 float4 per row; lane covers float4 positions lane+32k, k=0..2
    int4 sl[3];
    int  mn[3];
#pragma unroll
    for (int k = 0; k < 3; k++) {
        sl[k] = ((const int4*)s_slot)[lane + 32*k];
        mn[k] = min(min(sl[k].x, sl[k].y), min(sl[k].z, sl[k].w));
    }
#pragma unroll
    for (int r = 0; r < 8; r++) {
        int ch = warp * 8 + r;
        const float* vrow = &s_vals[ch * WPITCH];
        float* dst = out + rowbase + (size_t)ch * NYNX;
#pragma unroll
        for (int k = 0; k < 3; k++) {
            int4 s4 = sl[k];
            float4 v;
            v.x = (s4.x >= 0) ? vrow[s4.x] : 0.f;
            v.y = (s4.y >= 0) ? vrow[s4.y] : 0.f;
            v.z = (s4.z >= 0) ? vrow[s4.z] : 0.f;
            v.w = (s4.w >= 0) ? vrow[s4.w] : 0.f;
            float* d = dst + (lane + 32*k) * 4;
            if (mn[k] > -2) {
                __stcs((float4*)d, v);
            } else {  // contains a direct-stored cell: element-wise predicated
                if (s4.x != -2) d[0] = v.x;
                if (s4.y != -2) d[1] = v.y;
                if (s4.z != -2) d[2] = v.z;
                if (s4.w != -2) d[3] = v.w;
            }
        }
    }
}

// ---------------- launch: fork stats||vals via captured event edges ----------------
extern "C" void kernel_launch(void* const* d_in, const int* in_sizes, int n_in,
                              void* d_out, int out_size) {
    const float4* pil4    = (const float4*)d_in[0];
    const int4*   coords4 = (const int4*)d_in[1];
    const int*    nump    = (const int*)d_in[2];
    const float*  W       = (const float*)d_in[3];
    const float*  gamma   = (const float*)d_in[4];
    const float*  beta    = (const float*)d_in[5];
    float* out = (float*)d_out;

    static cudaStream_t s_side = nullptr;
    static cudaEvent_t  ev_fork = nullptr, ev_join = nullptr;
    if (s_side == nullptr) {
        cudaStreamCreateWithFlags(&s_side, cudaStreamNonBlocking);
        cudaEventCreateWithFlags(&ev_fork, cudaEventDisableTiming);
        cudaEventCreateWithFlags(&ev_join, cudaEventDisableTiming);
    }

    pre_init_kernel<<<592, 256>>>(W);

    // fork: side stream runs stats -> finalize, main stream runs vals
    cudaEventRecord(ev_fork, 0);
    cudaStreamWaitEvent(s_side, ev_fork, 0);

    stats_kernel<<<(NPIL + 255) / 256, 256, 0, s_side>>>(pil4, coords4, nump);
    finalize_kernel<<<1, 64, 0, s_side>>>(W, gamma, beta);
    cudaEventRecord(ev_join, s_side);

    vals_kernel<<<NPIL / 32, 256>>>(pil4);

    // join
    cudaStreamWaitEvent(0, ev_join, 0);
    dim3 grid(NWCHUNK, BATCH);
    writer_kernel<<<grid, 256>>>(out);
}

// round 14
// speedup vs baseline: 1.1964x; 1.0520x over previous
#include <cuda_runtime.h>
#include <cstdint>

#define NPIL   96000
#define MPTS   32
#define BATCH  8
#define NXc    432
#define NYc    496
#define NYNX   (NYc*NXc)          /* 214272 */
#define NCH    64
#define WCHUNK 256
#define NWCHUNK (NYNX / WCHUNK)   /* 837 exactly */
#define WMAX   64
#define WPITCH 65

// ---------------- device scratch (static, no allocation) ----------------
__device__ double d_stats[65];
__device__ float4 d_wbuf4[NPIL * 2];          // per pillar: (mx,my,mz,0),(cx,cy,cz,0)
__device__ int    d_winner[BATCH * NYNX];     // 6.9 MB
__device__ unsigned long long d_vals[NPIL * 32]; // 24.6 MB: u64 slot p*32+r = channels 2r,2r+1 (UNSCALED max)
__device__ unsigned long long d_UPK[32 * 4];  // channel-pair packed UNSCALED u (A,B,C,D)
__device__ unsigned long long d_GPK[32 * 7];  // channel-pair packed s*g0..g5, t
__device__ unsigned long long d_SPK[32];      // channel-pair packed s

// ---------------- f32x2 helpers ----------------
__device__ __forceinline__ unsigned long long splat2(float v) {
    unsigned long long r;
    asm("mov.b64 %0, {%1,%1};" : "=l"(r) : "f"(v));
    return r;
}
__device__ __forceinline__ unsigned long long pack2(float lo, float hi) {
    unsigned long long r;
    asm("mov.b64 %0, {%1,%2};" : "=l"(r) : "f"(lo), "f"(hi));
    return r;
}
#define FMA2(d, a, b)  asm("fma.rn.f32x2 %0, %1, %2, %0;" : "+l"(d) : "l"(a), "l"(b))
#define MUL2(d, a, b)  asm("mul.rn.f32x2 %0, %1, %2;"     : "=l"(d) : "l"(a), "l"(b))
#define UNPK2(lo, hi, d) asm("mov.b64 {%0,%1}, %2;" : "=f"(lo), "=f"(hi) : "l"(d))

// ---------------- pre-init: winner=-1, stats=0, pack unscaled U ----------------
__global__ void pre_init_kernel(const float* __restrict__ W) {
    int i = blockIdx.x * blockDim.x + threadIdx.x;
    int stride = gridDim.x * blockDim.x;
    const int nw = BATCH * NYNX;
    int4* w4 = (int4*)d_winner;
    int4 m1 = make_int4(-1, -1, -1, -1);
    for (int j = i; j < nw / 4; j += stride) w4[j] = m1;
    if (blockIdx.x == 0) {
        if (threadIdx.x < 65) d_stats[threadIdx.x] = 0.0;
        if (threadIdx.x >= 128 && threadIdx.x < 160) {
            int t = threadIdx.x - 128;
            int c0 = 2 * t, c1 = 2 * t + 1;
            float u0[4], u1[4];
            u0[0] = W[0*NCH+c0] + W[4*NCH+c0] + W[7*NCH+c0];
            u0[1] = W[1*NCH+c0] + W[5*NCH+c0] + W[8*NCH+c0];
            u0[2] = W[2*NCH+c0] + W[6*NCH+c0] + W[9*NCH+c0];
            u0[3] = W[3*NCH+c0];
            u1[0] = W[0*NCH+c1] + W[4*NCH+c1] + W[7*NCH+c1];
            u1[1] = W[1*NCH+c1] + W[5*NCH+c1] + W[8*NCH+c1];
            u1[2] = W[2*NCH+c1] + W[6*NCH+c1] + W[9*NCH+c1];
            u1[3] = W[3*NCH+c1];
#pragma unroll
            for (int k = 0; k < 4; k++) d_UPK[t*4 + k] = pack2(u0[k], u1[k]);
        }
    }
}

// ---------------- stats + winner + wbuf: one pass over pillar data ----------------
__global__ void __launch_bounds__(256) stats_kernel(const float4* __restrict__ pil4,
                             const int4*  __restrict__ coords4,
                             const int*   __restrict__ nump) {
    __shared__ float sred[8][65];
    int p = blockIdx.x * blockDim.x + threadIdx.x;
    int lane = threadIdx.x & 31;
    int warp = threadIdx.x >> 5;

    float acc[65];
#pragma unroll
    for (int i = 0; i < 65; i++) acc[i] = 0.f;

    if (p < NPIL) {
        float sx=0.f, sy=0.f, sz=0.f, sw=0.f;
        float xx=0.f,xy=0.f,xz=0.f,xw=0.f,yy=0.f,yz=0.f,yw=0.f,zz=0.f,zw=0.f,ww=0.f;
        const float4* vp = pil4 + (size_t)p * MPTS;
#pragma unroll 16
        for (int m = 0; m < MPTS; m++) {
            float4 v = vp[m];
            sx += v.x; sy += v.y; sz += v.z; sw += v.w;
            xx = fmaf(v.x, v.x, xx); xy = fmaf(v.x, v.y, xy);
            xz = fmaf(v.x, v.z, xz); xw = fmaf(v.x, v.w, xw);
            yy = fmaf(v.y, v.y, yy); yz = fmaf(v.y, v.z, yz);
            yw = fmaf(v.y, v.w, yw);
            zz = fmaf(v.z, v.z, zz); zw = fmaf(v.z, v.w, zw);
            ww = fmaf(v.w, v.w, ww);
        }
        int4 cd = coords4[p];                // (b, z, y, x)

        // winner scatter-order emulation (last index wins)
        int cell = cd.y + cd.z * NXc + cd.w;
        atomicMax(&d_winner[cd.x * NYNX + cell], p);

        float n = (float)nump[p];
        float mx = sx / n, my = sy / n, mz = sz / n;
        float ctrx = (float)cd.w * 0.16f + 0.08f;
        float ctry = (float)cd.z * 0.16f + (-39.6f);
        float ctrz = (float)cd.y * 4.0f  + (-1.0f);

        float sv[4] = {sx, sy, sz, sw};
        float w6[6] = {mx, my, mz, ctrx, ctry, ctrz};

        acc[0]=sx; acc[1]=sy; acc[2]=sz; acc[3]=sw;
        acc[4]=xx; acc[5]=xy; acc[6]=xz; acc[7]=xw; acc[8]=yy;
        acc[9]=yz; acc[10]=yw; acc[11]=zz; acc[12]=zw; acc[13]=ww;
#pragma unroll
        for (int j = 0; j < 6; j++) acc[14 + j] = w6[j];
#pragma unroll
        for (int i = 0; i < 4; i++)
#pragma unroll
            for (int j = 0; j < 6; j++) acc[20 + i*6 + j] = sv[i] * w6[j];
        {
            int k = 0;
#pragma unroll
            for (int i = 0; i < 6; i++)
#pragma unroll
                for (int j = i; j < 6; j++) { acc[44 + k] = w6[i] * w6[j]; k++; }
        }
        d_wbuf4[p*2 + 0] = make_float4(mx, my, mz, 0.f);
        d_wbuf4[p*2 + 1] = make_float4(ctrx, ctry, ctrz, 0.f);
    }

    // warp tree-reduce all 65 partials
#pragma unroll
    for (int i = 0; i < 65; i++) {
        float v = acc[i];
        v += __shfl_xor_sync(0xffffffffu, v, 16);
        v += __shfl_xor_sync(0xffffffffu, v, 8);
        v += __shfl_xor_sync(0xffffffffu, v, 4);
        v += __shfl_xor_sync(0xffffffffu, v, 2);
        v += __shfl_xor_sync(0xffffffffu, v, 1);
        acc[i] = v;
    }
    if (lane == 0) {
#pragma unroll
        for (int i = 0; i < 65; i++) sred[warp][i] = acc[i];
    }
    __syncthreads();

    if (threadIdx.x < 65) {
        float s = 0.f;
#pragma unroll
        for (int w = 0; w < 8; w++) s += sred[w][threadIdx.x];
        atomicAdd(&d_stats[threadIdx.x], (double)s);
    }
}

// ---------------- finalize: closed-form BN params, channel-pair packed ----------------
__global__ void finalize_kernel(const float* __restrict__ W,
                                const float* __restrict__ gamma,
                                const float* __restrict__ beta) {
    __shared__ float s_g[NCH][6];
    __shared__ float s_t[NCH];
    __shared__ float s_s[NCH];

    int c = threadIdx.x;
    if (c < NCH) {
        double A = (double)W[0*NCH+c] + (double)W[4*NCH+c] + (double)W[7*NCH+c];
        double Bv= (double)W[1*NCH+c] + (double)W[5*NCH+c] + (double)W[8*NCH+c];
        double Cv= (double)W[2*NCH+c] + (double)W[6*NCH+c] + (double)W[9*NCH+c];
        double Dv= (double)W[3*NCH+c];
        double u[4] = {A, Bv, Cv, Dv};
        double g[6];
#pragma unroll
        for (int j = 0; j < 6; j++) g[j] = (double)W[(4 + j)*NCH + c];

        double st[65];
#pragma unroll
        for (int i = 0; i < 65; i++) st[i] = d_stats[i];

        double S1 = u[0]*st[0] + u[1]*st[1] + u[2]*st[2] + u[3]*st[3];
        double sg = 0.0;
#pragma unroll
        for (int j = 0; j < 6; j++) sg += g[j] * st[14 + j];
        S1 -= (double)MPTS * sg;

        double Q1 = st[4]*A*A + st[8]*Bv*Bv + st[11]*Cv*Cv + st[13]*Dv*Dv
                  + 2.0*(st[5]*A*Bv + st[6]*A*Cv + st[7]*A*Dv
                       + st[9]*Bv*Cv + st[10]*Bv*Dv + st[12]*Cv*Dv);
        double Q2 = 0.0;
#pragma unroll
        for (int i = 0; i < 4; i++)
#pragma unroll
            for (int j = 0; j < 6; j++) Q2 += u[i] * st[20 + i*6 + j] * g[j];
        double Q3 = 0.0;
        {
            int k = 0;
#pragma unroll
            for (int i = 0; i < 6; i++)
#pragma unroll
                for (int j = i; j < 6; j++) {
                    Q3 += (i == j ? 1.0 : 2.0) * g[i] * g[j] * st[44 + k];
                    k++;
                }
        }
        double S2 = Q1 - 2.0*Q2 + (double)MPTS * Q3;

        double N   = (double)NPIL * (double)MPTS;
        double mu  = S1 / N;
        double var = S2 / N - mu * mu;
        double s   = (double)gamma[c] / sqrt(var + 1e-3);
        double t   = (double)beta[c] - s * mu;

#pragma unroll
        for (int j = 0; j < 6; j++) s_g[c][j] = (float)(s * g[j]);
        s_t[c] = (float)t;
        s_s[c] = (float)s;
    }
    __syncthreads();

    if (c < 32) {
        int c0 = 2 * c, c1 = 2 * c + 1;
#pragma unroll
        for (int j = 0; j < 6; j++) d_GPK[c*7 + j] = pack2(s_g[c0][j], s_g[c1][j]);
        d_GPK[c*7 + 6] = pack2(s_t[c0], s_t[c1]);
        d_SPK[c] = pack2(s_s[c0], s_s[c1]);
    }
}

// ---------------- vals: 16 threads/pillar x 2 pairs, 2 pillars/thread ----------------
// thread (ph, g): pillars {pbase+2ph, pbase+2ph+1}, pairs {g, 16+g}
// u64 slot p*32+r holds channel pair r (channels 2r, 2r+1) — pure pair order.
__global__ void __launch_bounds__(256) vals_kernel(const float4* __restrict__ pil4) {
    __shared__ float4 spts[32][33];   // 32 pillars/block, pitch 33 float4

    int tid = threadIdx.x;
    int ph  = tid >> 4;              // pillar-pair slot 0..15
    int g   = tid & 15;              // pair group: pairs {g, 16+g}
    int pbase = blockIdx.x * 32;

    // load 32 pillars (1024 float4) with 256 threads, coalesced
#pragma unroll
    for (int k = 0; k < 4; k++) {
        int idx = tid + k * 256;
        spts[idx >> 5][idx & 31] = pil4[(size_t)(pbase + (idx >> 5)) * MPTS + (idx & 31)];
    }

    int r0 = g, r1 = 16 + g;
    unsigned long long ux0 = d_UPK[r0*4+0], uy0 = d_UPK[r0*4+1],
                       uz0 = d_UPK[r0*4+2], uw0 = d_UPK[r0*4+3];
    unsigned long long ux1 = d_UPK[r1*4+0], uy1 = d_UPK[r1*4+1],
                       uz1 = d_UPK[r1*4+2], uw1 = d_UPK[r1*4+3];

    __syncthreads();

#pragma unroll
    for (int pp = 0; pp < 2; pp++) {
        int ps = 2 * ph + pp;
        int p  = pbase + ps;

        float q0 = -3.4e38f, q1 = -3.4e38f, q2 = -3.4e38f, q3 = -3.4e38f;
#pragma unroll 16
        for (int m = 0; m < MPTS; m++) {
            float4 v = spts[ps][m];
            unsigned long long vx = splat2(v.x);
            unsigned long long vy = splat2(v.y);
            unsigned long long vz = splat2(v.z);
            unsigned long long vw = splat2(v.w);
            unsigned long long d0, d1;
            MUL2(d0, vw, uw0); FMA2(d0, vz, uz0); FMA2(d0, vy, uy0); FMA2(d0, vx, ux0);
            MUL2(d1, vw, uw1); FMA2(d1, vz, uz1); FMA2(d1, vy, uy1); FMA2(d1, vx, ux1);
            float lo, hi;
            UNPK2(lo, hi, d0); q0 = fmaxf(q0, lo); q1 = fmaxf(q1, hi);
            UNPK2(lo, hi, d1); q2 = fmaxf(q2, lo); q3 = fmaxf(q3, hi);
        }

        // 16 consecutive g -> 128B coalesced u64 stores
        d_vals[(size_t)p * 32 + r0] = pack2(q0, q1);
        d_vals[(size_t)p * 32 + r1] = pack2(q2, q3);
    }
}

// ---------------- writer: affine+relu per winner, then coalesced stream ----------------
__global__ void __launch_bounds__(256) writer_kernel(float* __restrict__ out) {
    __shared__ int   s_slot[WCHUNK];    // -1 zero, 0..WMAX-1 slot, -2 direct-stored
    __shared__ int2  s_list[WCHUNK];    // (cell_local, pillar)
    __shared__ float s_vals[NCH * WPITCH];
    __shared__ int   s_n;

    int t    = threadIdx.x;
    int lane = t & 31;
    int warp = t >> 5;
    int b    = blockIdx.y;
    int c0   = blockIdx.x * WCHUNK;
    size_t rowbase = (size_t)b * NCH * NYNX + c0;

    if (t == 0) s_n = 0;
    __syncthreads();

    // --- phase 1: winners (coalesced) ---
    {
        int w = d_winner[b * NYNX + c0 + t];
        int slot = -1;
        if (w >= 0) {
            slot = atomicAdd(&s_n, 1);
            s_list[slot] = make_int2(t, w);
            if (slot >= WMAX) slot = -2;
        }
        s_slot[t] = slot;
    }
    __syncthreads();
    int n = s_n;

    // --- phase 2: gather M rows (pure pair order), apply BN affine + relu ---
    for (int idx = t; idx < n * 16; idx += 256) {
        int s = idx >> 4;
        int j = idx & 15;              // float4 idx j = pairs {2j, 2j+1} = channels 4j..4j+3
        int2 e = s_list[s];
        int p = e.y;

        int cbase = 4 * j;
        int r0 = 2 * j;

        float4 w0 = d_wbuf4[p*2 + 0];
        float4 w1 = d_wbuf4[p*2 + 1];
        unsigned long long nm0 = splat2(-w0.x), nm1 = splat2(-w0.y), nm2 = splat2(-w0.z);
        unsigned long long nc0 = splat2(-w1.x), nc1 = splat2(-w1.y), nc2 = splat2(-w1.z);

        ulonglong2 M2 = ((const ulonglong2*)d_vals)[(size_t)p * 16 + j];

        float v4[4];
#pragma unroll
        for (int k = 0; k < 2; k++) {
            int r = r0 + k;
            unsigned long long a = d_GPK[r*7 + 6];      // t2
            FMA2(a, nm0, d_GPK[r*7 + 0]);
            FMA2(a, nm1, d_GPK[r*7 + 1]);
            FMA2(a, nm2, d_GPK[r*7 + 2]);
            FMA2(a, nc0, d_GPK[r*7 + 3]);
            FMA2(a, nc1, d_GPK[r*7 + 4]);
            FMA2(a, nc2, d_GPK[r*7 + 5]);
            unsigned long long m = (k == 0) ? M2.x : M2.y;
            FMA2(a, m, d_SPK[r]);                       // s*M + cst
            float lo, hi;
            UNPK2(lo, hi, a);
            v4[2*k]     = fmaxf(lo, 0.f);
            v4[2*k + 1] = fmaxf(hi, 0.f);
        }

        if (s < WMAX) {
            s_vals[(cbase + 0) * WPITCH + s] = v4[0];
            s_vals[(cbase + 1) * WPITCH + s] = v4[1];
            s_vals[(cbase + 2) * WPITCH + s] = v4[2];
            s_vals[(cbase + 3) * WPITCH + s] = v4[3];
        } else {
            // overflow (astronomically rare): direct scattered store
            out[rowbase + (size_t)(cbase + 0) * NYNX + e.x] = v4[0];
            out[rowbase + (size_t)(cbase + 1) * NYNX + e.x] = v4[1];
            out[rowbase + (size_t)(cbase + 2) * NYNX + e.x] = v4[2];
            out[rowbase + (size_t)(cbase + 3) * NYNX + e.x] = v4[3];
        }
    }
    __syncthreads();

    // --- phase 3: stream all 64 channel rows. warp w -> channels 8w..8w+7 ---
    int4 sl0 = ((const int4*)s_slot)[lane];        // cells 4*lane .. 4*lane+3
    int4 sl1 = ((const int4*)s_slot)[lane + 32];   // cells 128+4*lane ..
    int mn0 = min(min(sl0.x, sl0.y), min(sl0.z, sl0.w));
    int mn1 = min(min(sl1.x, sl1.y), min(sl1.z, sl1.w));
#pragma unroll
    for (int r = 0; r < 8; r++) {
        int ch = warp * 8 + r;
        const float* vrow = &s_vals[ch * WPITCH];
        float* dst = out + rowbase + (size_t)ch * NYNX;

        float4 v0;
        v0.x = (sl0.x >= 0) ? vrow[sl0.x] : 0.f;
        v0.y = (sl0.y >= 0) ? vrow[sl0.y] : 0.f;
        v0.z = (sl0.z >= 0) ? vrow[sl0.z] : 0.f;
        v0.w = (sl0.w >= 0) ? vrow[sl0.w] : 0.f;
        if (mn0 > -2) {
            __stcs((float4*)(dst + lane * 4), v0);
        } else {
            if (sl0.x != -2) dst[lane*4 + 0] = v0.x;
            if (sl0.y != -2) dst[lane*4 + 1] = v0.y;
            if (sl0.z != -2) dst[lane*4 + 2] = v0.z;
            if (sl0.w != -2) dst[lane*4 + 3] = v0.w;
        }

        float4 v1;
        v1.x = (sl1.x >= 0) ? vrow[sl1.x] : 0.f;
        v1.y = (sl1.y >= 0) ? vrow[sl1.y] : 0.f;
        v1.z = (sl1.z >= 0) ? vrow[sl1.z] : 0.f;
        v1.w = (sl1.w >= 0) ? vrow[sl1.w] : 0.f;
        if (mn1 > -2) {
            __stcs((float4*)(dst + 128 + lane * 4), v1);
        } else {
            if (sl1.x != -2) dst[128 + lane*4 + 0] = v1.x;
            if (sl1.y != -2) dst[128 + lane*4 + 1] = v1.y;
            if (sl1.z != -2) dst[128 + lane*4 + 2] = v1.z;
            if (sl1.w != -2) dst[128 + lane*4 + 3] = v1.w;
        }
    }
}

// ---------------- launch: fork stats||vals via captured event edges ----------------
extern "C" void kernel_launch(void* const* d_in, const int* in_sizes, int n_in,
                              void* d_out, int out_size) {
    const float4* pil4    = (const float4*)d_in[0];
    const int4*   coords4 = (const int4*)d_in[1];
    const int*    nump    = (const int*)d_in[2];
    const float*  W       = (const float*)d_in[3];
    const float*  gamma   = (const float*)d_in[4];
    const float*  beta    = (const float*)d_in[5];
    float* out = (float*)d_out;

    static cudaStream_t s_side = nullptr;
    static cudaEvent_t  ev_fork = nullptr, ev_join = nullptr;
    if (s_side == nullptr) {
        cudaStreamCreateWithFlags(&s_side, cudaStreamNonBlocking);
        cudaEventCreateWithFlags(&ev_fork, cudaEventDisableTiming);
        cudaEventCreateWithFlags(&ev_join, cudaEventDisableTiming);
    }

    pre_init_kernel<<<592, 256>>>(W);

    // fork: side stream runs stats -> finalize, main stream runs vals
    cudaEventRecord(ev_fork, 0);
    cudaStreamWaitEvent(s_side, ev_fork, 0);

    stats_kernel<<<(NPIL + 255) / 256, 256, 0, s_side>>>(pil4, coords4, nump);
    finalize_kernel<<<1, 64, 0, s_side>>>(W, gamma, beta);
    cudaEventRecord(ev_join, s_side);

    vals_kernel<<<NPIL / 32, 256>>>(pil4);

    // join
    cudaStreamWaitEvent(0, ev_join, 0);
    dim3 grid(NWCHUNK, BATCH);
    writer_kernel<<<grid, 256>>>(out);
}